// round 1
// baseline (speedup 1.0000x reference)
#include <cuda_runtime.h>
#include <cuda_fp16.h>

// Problem constants (shapes fixed by the reference)
#define ROWS    64          // B*S = 4*16
#define DIM     512         // D
#define VOCAB   32000       // V
#define INNER   31999       // V-1 internal nodes
#define TDEPTH  18          // T
#define TROW    64000       // padded halves per row of table (2*32000)

// GEMM tiling
#define NT 64               // nodes per CTA
#define KT 64               // k tile
#define ATT_STRIDE 516      // padded float stride for att in smem (conflict-free)
#define SMEM_ATT   (ROWS*ATT_STRIDE*4)          // 132096 B
#define SMEM_WBUF  (2048*8)                     // 32 kp * 64 nodes * float2 = 16 KB
#define SMEM_K1    (SMEM_ATT + 2*SMEM_WBUF)     // 164864 B
#define SMEM_K2    128000                       // one fp16 table row (padded)

// -------- device globals (no runtime allocation allowed) --------
__device__ __align__(16) unsigned short g_off[TDEPTH * VOCAB];   // 1.152 MB
__device__ __align__(16) __half        g_table[(size_t)ROWS * TROW]; // 8.192 MB
__device__ int g_is64;

// -------- small PTX helpers --------
__device__ __forceinline__ unsigned smem_u32(const void* p) {
    return (unsigned)__cvta_generic_to_shared(p);
}
__device__ __forceinline__ unsigned long long ffma2(unsigned long long a,
                                                    unsigned long long b,
                                                    unsigned long long c) {
    unsigned long long d;
    asm("fma.rn.f32x2 %0, %1, %2, %3;" : "=l"(d) : "l"(a), "l"(b), "l"(c));
    return d;
}
__device__ __forceinline__ unsigned long long lds_u64(unsigned addr) {
    unsigned long long x;
    asm volatile("ld.shared.u64 %0, [%1];" : "=l"(x) : "r"(addr));
    return x;
}
__device__ __forceinline__ void lds_v2u64(unsigned long long& x, unsigned long long& y,
                                          unsigned addr) {
    asm volatile("ld.shared.v2.u64 {%0,%1}, [%2];" : "=l"(x), "=l"(y) : "r"(addr));
}
__device__ __forceinline__ void sts_v2f32(unsigned addr, float a, float b) {
    asm volatile("st.shared.v2.f32 [%0], {%1,%2};" :: "r"(addr), "f"(a), "f"(b));
}

// ================= K-1: detect int32 vs int64 path_index =================
// jax without x64 silently turns the declared int64 into int32; handle both.
// Values are in [0, 31999) so in the int64 case every odd 32-bit word is 0.
__global__ void k_detect(const int* __restrict__ p) {
    if (threadIdx.x == 0 && blockIdx.x == 0) {
        int flag = 1;
        #pragma unroll 1
        for (int i = 1; i < 128; i += 2)
            if (p[i] != 0) flag = 0;
        g_is64 = flag;
    }
}

// ================= K0: packed transposed offsets off[t][v] =================
__global__ void k_offsets(const int* __restrict__ pidx,
                          const float* __restrict__ pbias) {
    int v = blockIdx.x * 256 + threadIdx.x;
    int t = blockIdx.y;
    if (v >= VOCAB) return;
    int j = v * TDEPTH + t;
    int idx = g_is64 ? pidx[2 * j] : pidx[j];   // low word in LE int64 case
    int bit = (pbias[j] > 0.5f) ? 1 : 0;
    g_off[t * VOCAB + v] = (unsigned short)(idx * 2 + bit);
}

// ================= K1: GEMM + log-sigmoid table (fp16) =================
// CTA: 64 nodes x 64 rows. Thread (nx=tid&15, ry=tid>>4): nodes nx+16i, rows 4ry+j.
// att resident in smem (stride 516). Weight tiles double-buffered as float2
// k-pairs, k-major, XOR(kp&15) node swizzle -> conflict-free LDS.64 reads.
__global__ void __launch_bounds__(256, 1)
k_gemm(const float* __restrict__ att, const float* __restrict__ weight) {
    extern __shared__ char smem[];
    float* att_s = (float*)smem;
    const unsigned att_base = smem_u32(smem);
    const unsigned wbase0 = att_base + SMEM_ATT;
    const unsigned wbase1 = wbase0 + SMEM_WBUF;

    const int tid  = threadIdx.x;
    const int nx   = tid & 15;
    const int ry   = tid >> 4;
    const int base = blockIdx.x * NT;

    // ---- stage att[64][512] -> smem[64][516] (vectorized, coalesced) ----
    #pragma unroll 4
    for (int i = tid; i < ROWS * (DIM / 4); i += 256) {
        int r  = i >> 7;          // /128
        int k4 = i & 127;
        float4 v = *(const float4*)(att + r * DIM + k4 * 4);
        *(float4*)(att_s + r * ATT_STRIDE + k4 * 4) = v;
    }

    float4 stage[4];

    auto load_tile = [&](int kt) {
        #pragma unroll
        for (int u = 0; u < 4; u++) {
            int j   = tid + u * 256;       // 0..1023
            int nl  = j >> 4;              // node local 0..63
            int kk4 = j & 15;              // k-quad within tile
            int ng  = base + nl;
            if (ng < INNER)
                stage[u] = *(const float4*)(weight + (size_t)ng * DIM + kt * KT + kk4 * 4);
            else
                stage[u] = make_float4(0.f, 0.f, 0.f, 0.f);
        }
    };
    auto store_tile = [&](unsigned wb) {
        #pragma unroll
        for (int u = 0; u < 4; u++) {
            int j   = tid + u * 256;
            int nl  = j >> 4;
            int kk4 = j & 15;
            int kpa = kk4 * 2, kpb = kpa + 1;
            unsigned pa = kpa * 64 + (nl ^ (kpa & 15));
            unsigned pb = kpb * 64 + (nl ^ (kpb & 15));
            sts_v2f32(wb + pa * 8, stage[u].x, stage[u].y);
            sts_v2f32(wb + pb * 8, stage[u].z, stage[u].w);
        }
    };

    unsigned long long acc[4][4];
    #pragma unroll
    for (int i = 0; i < 4; i++)
        #pragma unroll
        for (int j = 0; j < 4; j++) acc[i][j] = 0ULL;

    unsigned rb[4];
    #pragma unroll
    for (int j = 0; j < 4; j++)
        rb[j] = att_base + (unsigned)((ry * 4 + j) * ATT_STRIDE) * 4u;

    load_tile(0);
    store_tile(wbase0);
    __syncthreads();

    const int NTILES = DIM / KT;   // 8
    for (int kt = 0; kt < NTILES; kt++) {
        if (kt + 1 < NTILES) load_tile(kt + 1);   // prefetch next tile to regs
        const unsigned wb = (kt & 1) ? wbase1 : wbase0;

        #pragma unroll 2
        for (int kq = 0; kq < KT / 4; kq++) {      // 16 iters, 4 k per iter
            const int kp0 = kq * 2, kp1 = kp0 + 1;
            const unsigned w0b = wb + kp0 * 512 + (unsigned)((nx ^ (kp0 & 15)) << 3);
            const unsigned w1b = wb + kp1 * 512 + (unsigned)((nx ^ (kp1 & 15)) << 3);
            unsigned long long w0[4], w1[4], alo[4], ahi[4];
            #pragma unroll
            for (int i = 0; i < 4; i++) {
                w0[i] = lds_u64(w0b + i * 128);
                w1[i] = lds_u64(w1b + i * 128);
            }
            const unsigned kbyte = (unsigned)((kt * KT + kq * 4) * 4);
            #pragma unroll
            for (int j = 0; j < 4; j++) lds_v2u64(alo[j], ahi[j], rb[j] + kbyte);
            #pragma unroll
            for (int i = 0; i < 4; i++)
                #pragma unroll
                for (int j = 0; j < 4; j++) {
                    acc[i][j] = ffma2(alo[j], w0[i], acc[i][j]);
                    acc[i][j] = ffma2(ahi[j], w1[i], acc[i][j]);
                }
        }

        if (kt + 1 < NTILES) {
            __syncthreads();                            // everyone done reading buf (kt-1)&1
            store_tile((kt & 1) ? wbase0 : wbase1);     // fill buffer (kt+1)&1
            __syncthreads();
        }
    }

    // ---- epilogue: x -> (log sigmoid(x), log(1-sigmoid(x))) as half2 ----
    #pragma unroll
    for (int i = 0; i < 4; i++) {
        int node = base + nx + 16 * i;
        #pragma unroll
        for (int j = 0; j < 4; j++) {
            int row = ry * 4 + j;
            float lo = __int_as_float((int)(acc[i][j] & 0xffffffffULL));
            float hi = __int_as_float((int)(acc[i][j] >> 32));
            float x  = lo + hi;
            float e  = __expf(-x);
            float sp = __logf(1.0f + e);   // softplus(-x)
            float t0 = -sp;                // log sigma(x)
            float t1 = -sp - x;            // log (1 - sigma(x))
            __half2 h = __floats2half2_rn(t0, t1);
            // padded row stride absorbs the one out-of-range node (31999)
            *(__half2*)(g_table + (size_t)row * TROW + 2 * node) = h;
        }
    }
}

// ================= K2: smem-resident gather + depth sum =================
// CTA = (row, vocab-half). The 128 KB fp16 table row lives in shared memory;
// all 18 gathers per output are LDS (random-bank, ~3-4 way avg conflicts).
__global__ void __launch_bounds__(512, 1)
k_gather(float* __restrict__ out) {
    extern __shared__ char smem[];
    __half* hs = (__half*)smem;
    const int tid = threadIdx.x;
    const int row = blockIdx.x >> 1;
    const int vh  = blockIdx.x & 1;

    // load this row's table: 128000 B = 8000 uint4
    const uint4* src = (const uint4*)(g_table + (size_t)row * TROW);
    uint4* dst = (uint4*)smem;
    #pragma unroll 4
    for (int i = tid; i < TROW / 8; i += 512) dst[i] = src[i];
    __syncthreads();

    const int vend = vh * 16000 + 16000;
    for (int v = vh * 16000 + tid; v < vend; v += 512) {
        float a0 = 0.f, a1 = 0.f;   // 2 accumulators for ILP
        #pragma unroll
        for (int t = 0; t < TDEPTH; t += 2) {
            unsigned o0 = g_off[t * VOCAB + v];
            unsigned o1 = g_off[(t + 1) * VOCAB + v];
            a0 += __half2float(hs[o0]);
            a1 += __half2float(hs[o1]);
        }
        out[row * VOCAB + v] = a0 + a1;
    }
}

// ================= launch =================
extern "C" void kernel_launch(void* const* d_in, const int* in_sizes, int n_in,
                              void* d_out, int out_size) {
    const float* att    = (const float*)d_in[0];
    const float* weight = (const float*)d_in[1];
    const int*   pidx   = (const int*)d_in[2];   // int32 or int64 (detected)
    const float* pbias  = (const float*)d_in[4];
    float* out = (float*)d_out;

    cudaFuncSetAttribute(k_gemm,   cudaFuncAttributeMaxDynamicSharedMemorySize, SMEM_K1);
    cudaFuncSetAttribute(k_gather, cudaFuncAttributeMaxDynamicSharedMemorySize, SMEM_K2);

    k_detect<<<1, 32>>>(pidx);

    dim3 g0((VOCAB + 255) / 256, TDEPTH);
    k_offsets<<<g0, 256>>>(pidx, pbias);

    k_gemm<<<(VOCAB + NT - 1) / NT, 256, SMEM_K1>>>(att, weight);   // 500 CTAs

    k_gather<<<ROWS * 2, 512, SMEM_K2>>>(out);                      // 128 CTAs
}

// round 2
// speedup vs baseline: 2.8347x; 2.8347x over previous
#include <cuda_runtime.h>
#include <cuda_fp16.h>

// Problem constants
#define ROWS    64          // B*S
#define DIM     512         // D
#define VOCAB   32000       // V
#define INNER   31999       // V-1
#define TDEPTH  18          // T

// GEMM tiling
#define CTA_N   128
#define KT      64
#define A_STRIDE 520        // halves, 4m-bank-rotation -> ldmatrix conflict-free
#define W_STRIDE 72         // halves, 4n-bank-rotation -> ldmatrix conflict-free
#define SMEM_ATT_H (ROWS*A_STRIDE*2)           // 66560
#define SMEM_WT    (CTA_N*W_STRIDE*2)          // 18432
#define SMEM_K1    (SMEM_ATT_H + 2*SMEM_WT)    // 103424

// -------- device globals (no runtime allocation allowed) --------
// transposed table: entry (node2, row) -> fp16 log-prob; node2 = 2*node + bit
__device__ __align__(16) __half   g_tableT[(size_t)2 * VOCAB * ROWS];  // 8.192 MB
__device__ __align__(16) unsigned g_off32[TDEPTH * VOCAB];             // byte offsets node2*128
__device__ int g_is64;

// -------- PTX helpers --------
__device__ __forceinline__ unsigned smem_u32(const void* p) {
    return (unsigned)__cvta_generic_to_shared(p);
}
__device__ __forceinline__ void ldmx4(unsigned& r0, unsigned& r1, unsigned& r2, unsigned& r3,
                                      unsigned addr) {
    asm volatile("ldmatrix.sync.aligned.m8n8.x4.shared.b16 {%0,%1,%2,%3}, [%4];"
                 : "=r"(r0), "=r"(r1), "=r"(r2), "=r"(r3) : "r"(addr));
}
__device__ __forceinline__ void mma16816(float* d,
                                         unsigned a0, unsigned a1, unsigned a2, unsigned a3,
                                         unsigned b0, unsigned b1) {
    asm volatile("mma.sync.aligned.m16n8k16.row.col.f32.f16.f16.f32 "
                 "{%0,%1,%2,%3}, {%4,%5,%6,%7}, {%8,%9}, {%0,%1,%2,%3};"
                 : "+f"(d[0]), "+f"(d[1]), "+f"(d[2]), "+f"(d[3])
                 : "r"(a0), "r"(a1), "r"(a2), "r"(a3), "r"(b0), "r"(b1));
}
__device__ __forceinline__ void sts_v2u32(unsigned addr, unsigned a, unsigned b) {
    asm volatile("st.shared.v2.u32 [%0], {%1,%2};" :: "r"(addr), "r"(a), "r"(b));
}

// ================= detect int32 vs int64 path_index =================
__global__ void k_detect(const int* __restrict__ p) {
    int l = threadIdx.x;
    int v = p[2 * l + 1];                          // odd words are 0 iff int64
    unsigned m = __ballot_sync(0xffffffffu, v != 0);
    if (l == 0) g_is64 = (m == 0) ? 1 : 0;
}

// ================= byte offsets off[t][v] = (2*idx+bit)*128 =================
__global__ void k_offsets(const int* __restrict__ pidx,
                          const float* __restrict__ pbias) {
    int v = blockIdx.x * 256 + threadIdx.x;
    int t = blockIdx.y;
    if (v >= VOCAB) return;
    int j = v * TDEPTH + t;
    int idx = g_is64 ? pidx[2 * j] : pidx[j];      // low word in LE int64 case
    int bit = (pbias[j] > 0.5f) ? 1 : 0;
    g_off32[t * VOCAB + v] = (unsigned)(idx * 2 + bit) << 7;   // *128 bytes
}

// ================= GEMM via mma.sync + log-sigmoid epilogue =================
// CTA: 128 nodes x 64 rows, 8 warps (wm=warp/2 rows, wn=warp&1 node-half).
// att fp16 resident in smem (stride 520h); weight fp32->fp16 double-buffered
// tiles (stride 72h). Both strides give conflict-free ldmatrix.
__global__ void __launch_bounds__(256)
k_gemm(const float* __restrict__ att, const float* __restrict__ weight) {
    extern __shared__ char smem[];
    const unsigned att_base = smem_u32(smem);
    const unsigned wb0 = att_base + SMEM_ATT_H;
    const unsigned wb1 = wb0 + SMEM_WT;

    const int tid  = threadIdx.x;
    const int lane = tid & 31;
    const int warp = tid >> 5;
    const int wm   = warp >> 1;       // 0..3  (row block of 16)
    const int wn   = warp & 1;        // 0..1  (node block of 64)
    const int base = blockIdx.x * CTA_N;

    // ---- stage att[64][512] fp32 -> fp16 smem (stride 520) ----
    #pragma unroll 4
    for (int i = tid; i < ROWS * (DIM / 4); i += 256) {
        int r = i >> 7, k4 = i & 127;
        float4 vv = *(const float4*)(att + r * DIM + k4 * 4);
        __half2 p0 = __floats2half2_rn(vv.x, vv.y);
        __half2 p1 = __floats2half2_rn(vv.z, vv.w);
        unsigned addr = att_base + (unsigned)(r * A_STRIDE + k4 * 4) * 2u;
        sts_v2u32(addr, *(unsigned*)&p0, *(unsigned*)&p1);
    }

    float4 st[8];
    auto load_w = [&](int kt) {
        #pragma unroll
        for (int u = 0; u < 8; u++) {
            int idx = tid + u * 256;
            int row = idx >> 4, c4 = idx & 15;
            int ng = base + row;
            if (ng < INNER)
                st[u] = *(const float4*)(weight + (size_t)ng * DIM + kt * KT + c4 * 4);
            else
                st[u] = make_float4(0.f, 0.f, 0.f, 0.f);
        }
    };
    auto store_w = [&](unsigned wb) {
        #pragma unroll
        for (int u = 0; u < 8; u++) {
            int idx = tid + u * 256;
            int row = idx >> 4, c4 = idx & 15;
            __half2 p0 = __floats2half2_rn(st[u].x, st[u].y);
            __half2 p1 = __floats2half2_rn(st[u].z, st[u].w);
            unsigned addr = wb + (unsigned)(row * W_STRIDE + c4 * 4) * 2u;
            sts_v2u32(addr, *(unsigned*)&p0, *(unsigned*)&p1);
        }
    };

    float acc[8][4];
    #pragma unroll
    for (int i = 0; i < 8; i++)
        #pragma unroll
        for (int j = 0; j < 4; j++) acc[i][j] = 0.f;

    // ldmatrix per-lane base offsets (non-trans, fragment layouts verified)
    const unsigned a_off = att_base +
        (unsigned)((wm * 16 + (lane & 15)) * A_STRIDE + ((lane >> 4) << 3)) * 2u;
    const unsigned b_off =
        (unsigned)((wn * 64 + (lane & 7) + ((lane >> 4) << 3)) * W_STRIDE
                   + (((lane >> 3) & 1) << 3)) * 2u;

    load_w(0);
    store_w(wb0);
    __syncthreads();

    const int NTILES = DIM / KT;       // 8
    for (int kt = 0; kt < NTILES; kt++) {
        if (kt + 1 < NTILES) load_w(kt + 1);
        const unsigned wb = (kt & 1) ? wb1 : wb0;
        #pragma unroll
        for (int k16 = 0; k16 < 4; k16++) {
            unsigned a0, a1, a2, a3;
            ldmx4(a0, a1, a2, a3, a_off + (unsigned)((kt * KT + k16 * 16) * 2));
            #pragma unroll
            for (int nt = 0; nt < 4; nt++) {
                unsigned b0, b1, b2, b3;
                ldmx4(b0, b1, b2, b3,
                      wb + b_off + (unsigned)((nt * 16 * W_STRIDE + k16 * 16) * 2));
                mma16816(acc[2 * nt + 0], a0, a1, a2, a3, b0, b1);
                mma16816(acc[2 * nt + 1], a0, a1, a2, a3, b2, b3);
            }
        }
        __syncthreads();
        if (kt + 1 < NTILES) {
            store_w((kt & 1) ? wb0 : wb1);
            __syncthreads();
        }
    }

    // ---- epilogue: x -> (log sigma(x), log(1-sigma(x))) fp16, transposed table ----
    const int r0 = wm * 16 + (lane >> 2);
    const int c0 = base + wn * 64 + 2 * (lane & 3);
    #pragma unroll
    for (int nt = 0; nt < 8; nt++) {
        int n_base = c0 + nt * 8;
        #pragma unroll
        for (int ri = 0; ri < 2; ri++) {
            int row = r0 + ri * 8;
            #pragma unroll
            for (int ci = 0; ci < 2; ci++) {
                float x = acc[nt][ri * 2 + ci];
                int n = n_base + ci;
                float e  = __expf(-x);
                float sp = __logf(1.0f + e);     // softplus(-x)
                g_tableT[(size_t)(2 * n) * ROWS + row]     = __float2half_rn(-sp);
                g_tableT[(size_t)(2 * n + 1) * ROWS + row] = __float2half_rn(-sp - x);
            }
        }
    }
}

// ================= gather: coalesced 128B row-vector loads =================
// Warp handles 2 vocab entries (one per half-warp). Lane loads 8B = 4 rows of
// the 128B node-row. 18 depths accumulate in float4. Smem transpose stage for
// coalesced float2 output stores.
__global__ void __launch_bounds__(256)
k_gather(float* __restrict__ out) {
    __shared__ __align__(16) float stage[ROWS * 66];   // [row][66] padded
    const int tid  = threadIdx.x;
    const int lane = tid & 31;
    const int w    = tid >> 5;          // 8 warps
    const int hw   = lane >> 4;         // half-warp -> which v of the pair
    const int l15  = lane & 15;         // 4-row group within 64 rows
    const int vbase = blockIdx.x * 64;
    const char* tb = (const char*)g_tableT;

    #pragma unroll 2
    for (int p = 0; p < 4; p++) {
        const int vl = w * 8 + p * 2 + hw;      // 0..63
        const int v  = vbase + vl;
        float4 a = make_float4(0.f, 0.f, 0.f, 0.f);
        #pragma unroll
        for (int t = 0; t < TDEPTH; t++) {
            unsigned ob = g_off32[t * VOCAB + v];          // uniform per half-warp
            uint2 q = *(const uint2*)(tb + ob + (l15 << 3));
            float2 f0 = __half22float2(*(__half2*)&q.x);
            float2 f1 = __half22float2(*(__half2*)&q.y);
            a.x += f0.x; a.y += f0.y; a.z += f1.x; a.w += f1.y;
        }
        const int r = 4 * l15;
        stage[(r + 0) * 66 + vl] = a.x;
        stage[(r + 1) * 66 + vl] = a.y;
        stage[(r + 2) * 66 + vl] = a.z;
        stage[(r + 3) * 66 + vl] = a.w;
    }
    __syncthreads();

    // writeback: warp w covers rows w, w+8, ...; lane covers v-pair 2*lane
    #pragma unroll
    for (int rr = 0; rr < 8; rr++) {
        const int r = w + rr * 8;
        float2 f = *(const float2*)&stage[r * 66 + 2 * lane];
        *(float2*)(out + (size_t)r * VOCAB + vbase + 2 * lane) = f;
    }
}

// ================= launch =================
extern "C" void kernel_launch(void* const* d_in, const int* in_sizes, int n_in,
                              void* d_out, int out_size) {
    const float* att    = (const float*)d_in[0];
    const float* weight = (const float*)d_in[1];
    const int*   pidx   = (const int*)d_in[2];   // int32 or int64 (detected)
    const float* pbias  = (const float*)d_in[4];
    float* out = (float*)d_out;

    cudaFuncSetAttribute(k_gemm, cudaFuncAttributeMaxDynamicSharedMemorySize, SMEM_K1);

    k_detect<<<1, 32>>>(pidx);

    dim3 g0((VOCAB + 255) / 256, TDEPTH);
    k_offsets<<<g0, 256>>>(pidx, pbias);

    k_gemm<<<VOCAB / CTA_N, 256, SMEM_K1>>>(att, weight);   // 250 CTAs

    k_gather<<<VOCAB / 64, 256>>>(out);                     // 500 CTAs
}